// round 6
// baseline (speedup 1.0000x reference)
#include <cuda_runtime.h>
#include <cuda_bf16.h>
#include <mma.h>
#include <cstdint>

using namespace nvcuda;

// ---------------- problem constants ----------------
#define BATCH   8
#define NT      8192
#define NS      2048
#define NTOT    (BATCH * NT)      // 65536 target rows
#define C_TGT   128
#define C_SRC   256
#define C_IN    384
#define C_HID   256
#define C_OUT   128

// ---------------- device scratch (no allocs allowed) ----------------
__device__ __align__(128) int   g_knn_idx[NTOT * 3];
__device__ __align__(128) float g_knn_w  [NTOT * 3];
__device__ __align__(128) float g_interp [NTOT * C_SRC];   // 64 MB
__device__ __align__(128) float g_hidden [NTOT * C_HID];   // 64 MB

// ============================================================
// cp.async helpers (LDGSTS 16B)
// ============================================================
__device__ __forceinline__ void cp16(float* dst_smem, const float* src_gmem) {
    uint32_t d = (uint32_t)__cvta_generic_to_shared(dst_smem);
    asm volatile("cp.async.cg.shared.global [%0], [%1], 16;\n" :: "r"(d), "l"(src_gmem));
}
__device__ __forceinline__ void cp_commit() {
    asm volatile("cp.async.commit_group;\n");
}
__device__ __forceinline__ void cp_wait_all() {
    asm volatile("cp.async.wait_group 0;\n");
}

// ============================================================
// Kernel 1: brute-force 3-NN per target within its batch.
// ============================================================
__global__ __launch_bounds__(256)
void knn_kernel(const float* __restrict__ pos_t, const float* __restrict__ pos_s)
{
    __shared__ float4 sp[NS];             // 32 KB
    const int b    = blockIdx.x >> 5;
    const int tile = blockIdx.x & 31;

    const float* ps = pos_s + (size_t)b * NS * 3;
    for (int s = threadIdx.x; s < NS; s += 256) {
        sp[s] = make_float4(ps[3*s], ps[3*s+1], ps[3*s+2], 0.f);
    }
    __syncthreads();

    const int t = (b * 32 + tile) * 256 + threadIdx.x;
    const float tx = pos_t[3*t], ty = pos_t[3*t+1], tz = pos_t[3*t+2];

    float d0 = 1e30f, d1 = 1e30f, d2 = 1e30f;
    int   i0 = 0,     i1 = 0,     i2 = 0;

    #pragma unroll 4
    for (int s = 0; s < NS; ++s) {
        float4 p = sp[s];
        float dx = tx - p.x, dy = ty - p.y, dz = tz - p.z;
        float d  = fmaf(dz, dz, fmaf(dy, dy, dx * dx));
        if (d < d2) {
            if (d < d1) {
                d2 = d1; i2 = i1;
                if (d < d0) { d1 = d0; i1 = i0; d0 = d; i0 = s; }
                else        { d1 = d;  i1 = s; }
            } else { d2 = d; i2 = s; }
        }
    }

    const float w0 = 1.f / fmaxf(d0, 1e-16f);
    const float w1 = 1.f / fmaxf(d1, 1e-16f);
    const float w2 = 1.f / fmaxf(d2, 1e-16f);
    const float inv = 1.f / (w0 + w1 + w2);

    g_knn_w[3*t+0] = w0 * inv;
    g_knn_w[3*t+1] = w1 * inv;
    g_knn_w[3*t+2] = w2 * inv;
    g_knn_idx[3*t+0] = b * NS + i0;
    g_knn_idx[3*t+1] = b * NS + i1;
    g_knn_idx[3*t+2] = b * NS + i2;
}

// ============================================================
// Kernel 2: interpolation gather. One warp per target row.
// ============================================================
__global__ __launch_bounds__(256)
void interp_kernel(const float* __restrict__ xs)
{
    const int row  = blockIdx.x * 8 + (threadIdx.x >> 5);
    const int lane = threadIdx.x & 31;

    const int   i0 = g_knn_idx[3*row+0];
    const int   i1 = g_knn_idx[3*row+1];
    const int   i2 = g_knn_idx[3*row+2];
    const float w0 = g_knn_w[3*row+0];
    const float w1 = g_knn_w[3*row+1];
    const float w2 = g_knn_w[3*row+2];

    const float4* s0 = (const float4*)(xs + (size_t)i0 * C_SRC);
    const float4* s1 = (const float4*)(xs + (size_t)i1 * C_SRC);
    const float4* s2 = (const float4*)(xs + (size_t)i2 * C_SRC);
    float4* dst = (float4*)(g_interp + (size_t)row * C_SRC);

    #pragma unroll
    for (int h = 0; h < 2; ++h) {
        const int c = lane + h * 32;
        float4 a = s0[c], b = s1[c], d = s2[c];
        float4 r;
        r.x = w0*a.x + w1*b.x + w2*d.x;
        r.y = w0*a.y + w1*b.y + w2*d.y;
        r.z = w0*a.z + w1*b.z + w2*d.z;
        r.w = w0*a.w + w1*b.w + w2*d.w;
        dst[c] = r;
    }
}

// ============================================================
// GEMM machinery: 128x128 block tile, 8 warps (4x2), KC=32,
// wmma tf32 m16n16k8, cp.async 2-stage double buffer.
// ============================================================
#define SA_LD 36
#define SB_LD 132
#define SA_SZ (128 * SA_LD)          // 4608 floats
#define SB_SZ (32 * SB_LD)           // 4224 floats
#define STG_SZ (SA_SZ + SB_SZ)       // 8832 floats / stage
#define SMEM_BYTES (2 * STG_SZ * 4)  // 70656 bytes

using FragA = wmma::fragment<wmma::matrix_a, 16, 16, 8, wmma::precision::tf32, wmma::row_major>;
using FragB = wmma::fragment<wmma::matrix_b, 16, 16, 8, wmma::precision::tf32, wmma::row_major>;
using FragC = wmma::fragment<wmma::accumulator, 16, 16, 8, float>;

// stage one 128x32 A tile + 32x128 B tile via cp.async (raw fp32)
__device__ __forceinline__ void stage_tiles(
    float* sA, float* sB, int tid, int m0,
    const float* abase, int astride, int aoff,
    const float* bbase, int bstride, int boff, int n0)
{
    #pragma unroll
    for (int tI = 0; tI < 4; ++tI) {
        const int i4 = tid + tI * 256;           // 1024 chunks of 16B
        const int r  = i4 >> 3;
        const int c4 = (i4 & 7) << 2;
        cp16(&sA[r * SA_LD + c4], abase + (size_t)(m0 + r) * astride + aoff + c4);
    }
    #pragma unroll
    for (int tI = 0; tI < 4; ++tI) {
        const int i4 = tid + tI * 256;
        const int r  = i4 >> 5;
        const int c4 = (i4 & 31) << 2;
        cp16(&sB[r * SB_LD + c4], bbase + (size_t)(boff + r) * bstride + n0 + c4);
    }
}

// consume one staged K=32 chunk: convert to tf32 in-fragment, 32 MMAs/warp
__device__ __forceinline__ void compute_chunk(
    const float* sA, const float* sB, int warp_m, int warp_n, FragC fc[2][4])
{
    #pragma unroll
    for (int kk = 0; kk < 4; ++kk) {
        FragA fa[2];
        FragB fb[4];
        #pragma unroll
        for (int i = 0; i < 2; ++i) {
            wmma::load_matrix_sync(fa[i], &sA[(warp_m*32 + i*16) * SA_LD + kk*8], SA_LD);
            #pragma unroll
            for (int t = 0; t < fa[i].num_elements; ++t)
                fa[i].x[t] = wmma::__float_to_tf32(fa[i].x[t]);
        }
        #pragma unroll
        for (int j = 0; j < 4; ++j) {
            wmma::load_matrix_sync(fb[j], &sB[(kk*8) * SB_LD + warp_n*64 + j*16], SB_LD);
            #pragma unroll
            for (int t = 0; t < fb[j].num_elements; ++t)
                fb[j].x[t] = wmma::__float_to_tf32(fb[j].x[t]);
        }
        #pragma unroll
        for (int i = 0; i < 2; ++i)
            #pragma unroll
            for (int j = 0; j < 4; ++j)
                wmma::mma_sync(fc[i][j], fa[i], fb[j], fc[i][j]);
    }
}

// ------------------------------------------------------------
// GEMM1: h = relu([x_target | interp] @ W1 + b1)   K=384, N=256
// ------------------------------------------------------------
__global__ __launch_bounds__(256, 2)
void gemm1_kernel(const float* __restrict__ xt,
                  const float* __restrict__ W1,
                  const float* __restrict__ b1)
{
    extern __shared__ float smem[];
    const int m0 = blockIdx.x * 128;
    const int n0 = blockIdx.y * 128;
    const int tid = threadIdx.x;
    const int w   = tid >> 5;
    const int warp_m = w & 3;
    const int warp_n = w >> 2;
    const int lane = tid & 31;

    FragC fc[2][4];
    #pragma unroll
    for (int i = 0; i < 2; ++i)
        #pragma unroll
        for (int j = 0; j < 4; ++j)
            wmma::fill_fragment(fc[i][j], 0.f);

    auto asrc = [&](int kc, const float*& ab, int& as, int& ao) {
        if (kc < C_TGT) { ab = xt;       as = C_TGT; ao = kc;         }
        else            { ab = g_interp; as = C_SRC; ao = kc - C_TGT; }
    };

    // prologue: stage chunk 0 into stage 0
    {
        const float* ab; int as, ao;
        asrc(0, ab, as, ao);
        stage_tiles(smem, smem + SA_SZ, tid, m0, ab, as, ao, W1, C_HID, 0, n0);
        cp_commit();
    }

    const int NITER = C_IN / 32;   // 12
    for (int it = 0; it < NITER; ++it) {
        const int cur = it & 1;
        cp_wait_all();
        __syncthreads();          // cur tile ready; prev compute on 1-cur done
        if (it + 1 < NITER) {
            const int kc = (it + 1) * 32;
            const float* ab; int as, ao;
            asrc(kc, ab, as, ao);
            float* st = smem + (1 - cur) * STG_SZ;
            stage_tiles(st, st + SA_SZ, tid, m0, ab, as, ao, W1, C_HID, kc, n0);
            cp_commit();
        }
        const float* st = smem + cur * STG_SZ;
        compute_chunk(st, st + SA_SZ, warp_m, warp_n, fc);
    }
    __syncthreads();

    // epilogue: bias + relu -> g_hidden
    float* wb = &smem[w * 1024];
    const int gm_base = m0 + warp_m * 32;
    const int gn_base = n0 + warp_n * 64;
    #pragma unroll
    for (int i = 0; i < 2; ++i) {
        #pragma unroll
        for (int j = 0; j < 4; ++j)
            wmma::store_matrix_sync(wb + j*16, fc[i][j], 64, wmma::mem_row_major);
        __syncwarp();
        #pragma unroll
        for (int e = lane; e < 256; e += 32) {
            const int rr = e >> 4;
            const int cc = (e & 15) << 2;
            float4 v = *(float4*)(wb + rr*64 + cc);
            const int gn = gn_base + cc;
            v.x = fmaxf(v.x + b1[gn+0], 0.f);
            v.y = fmaxf(v.y + b1[gn+1], 0.f);
            v.z = fmaxf(v.z + b1[gn+2], 0.f);
            v.w = fmaxf(v.w + b1[gn+3], 0.f);
            *(float4*)(&g_hidden[(size_t)(gm_base + i*16 + rr) * C_HID + gn]) = v;
        }
        __syncwarp();
    }
}

// ------------------------------------------------------------
// GEMM2: out = relu([h | x_target | interp] @ [W2; Ws] + (b2+bs))
// K=640, N=128
// ------------------------------------------------------------
__global__ __launch_bounds__(256, 2)
void gemm2_kernel(const float* __restrict__ xt,
                  const float* __restrict__ W2,
                  const float* __restrict__ b2,
                  const float* __restrict__ Ws,
                  const float* __restrict__ bs,
                  float* __restrict__ out)
{
    extern __shared__ float smem[];
    const int m0 = blockIdx.x * 128;
    const int tid = threadIdx.x;
    const int w   = tid >> 5;
    const int warp_m = w & 3;
    const int warp_n = w >> 2;
    const int lane = tid & 31;

    FragC fc[2][4];
    #pragma unroll
    for (int i = 0; i < 2; ++i)
        #pragma unroll
        for (int j = 0; j < 4; ++j)
            wmma::fill_fragment(fc[i][j], 0.f);

    auto srcs = [&](int kc, const float*& ab, int& as, int& ao,
                    const float*& bb, int& bo) {
        if      (kc < 256) { ab = g_hidden; as = C_HID; ao = kc;       }
        else if (kc < 384) { ab = xt;       as = C_TGT; ao = kc - 256; }
        else               { ab = g_interp; as = C_SRC; ao = kc - 384; }
        if (kc < 256) { bb = W2; bo = kc;       }
        else          { bb = Ws; bo = kc - 256; }
    };

    {
        const float* ab; const float* bb; int as, ao, bo;
        srcs(0, ab, as, ao, bb, bo);
        stage_tiles(smem, smem + SA_SZ, tid, m0, ab, as, ao, bb, C_OUT, bo, 0);
        cp_commit();
    }

    const int NITER = 640 / 32;   // 20
    for (int it = 0; it < NITER; ++it) {
        const int cur = it & 1;
        cp_wait_all();
        __syncthreads();
        if (it + 1 < NITER) {
            const int kc = (it + 1) * 32;
            const float* ab; const float* bb; int as, ao, bo;
            srcs(kc, ab, as, ao, bb, bo);
            float* st = smem + (1 - cur) * STG_SZ;
            stage_tiles(st, st + SA_SZ, tid, m0, ab, as, ao, bb, C_OUT, bo, 0);
            cp_commit();
        }
        const float* st = smem + cur * STG_SZ;
        compute_chunk(st, st + SA_SZ, warp_m, warp_n, fc);
    }
    __syncthreads();

    // epilogue: (b2+bs) + relu -> out
    float* wb = &smem[w * 1024];
    const int gm_base = m0 + warp_m * 32;
    const int gn_base = warp_n * 64;
    #pragma unroll
    for (int i = 0; i < 2; ++i) {
        #pragma unroll
        for (int j = 0; j < 4; ++j)
            wmma::store_matrix_sync(wb + j*16, fc[i][j], 64, wmma::mem_row_major);
        __syncwarp();
        #pragma unroll
        for (int e = lane; e < 256; e += 32) {
            const int rr = e >> 4;
            const int cc = (e & 15) << 2;
            float4 v = *(float4*)(wb + rr*64 + cc);
            const int gn = gn_base + cc;
            v.x = fmaxf(v.x + b2[gn+0] + bs[gn+0], 0.f);
            v.y = fmaxf(v.y + b2[gn+1] + bs[gn+1], 0.f);
            v.z = fmaxf(v.z + b2[gn+2] + bs[gn+2], 0.f);
            v.w = fmaxf(v.w + b2[gn+3] + bs[gn+3], 0.f);
            *(float4*)(&out[(size_t)(gm_base + i*16 + rr) * C_OUT + gn]) = v;
        }
        __syncwarp();
    }
}

// ============================================================
// Launch.
// ============================================================
extern "C" void kernel_launch(void* const* d_in, const int* in_sizes, int n_in,
                              void* d_out, int out_size)
{
    const float* xt = (const float*)d_in[0];
    const float* pt = (const float*)d_in[1];
    const float* xs = (const float*)d_in[3];
    const float* ps = (const float*)d_in[4];
    const float* W1 = (const float*)d_in[6];
    const float* b1 = (const float*)d_in[7];
    const float* W2 = (const float*)d_in[8];
    const float* b2 = (const float*)d_in[9];
    const float* Ws = (const float*)d_in[10];
    const float* bs = (const float*)d_in[11];
    float* out = (float*)d_out;

    static bool attr_set = false;
    if (!attr_set) {
        cudaFuncSetAttribute(gemm1_kernel, cudaFuncAttributeMaxDynamicSharedMemorySize, SMEM_BYTES);
        cudaFuncSetAttribute(gemm2_kernel, cudaFuncAttributeMaxDynamicSharedMemorySize, SMEM_BYTES);
        attr_set = true;
    }

    knn_kernel   <<<BATCH * (NT / 256), 256>>>(pt, ps);
    interp_kernel<<<NTOT / 8, 256>>>(xs);
    gemm1_kernel <<<dim3(NTOT / 128, C_HID / 128), 256, SMEM_BYTES>>>(xt, W1, b1);
    gemm2_kernel <<<dim3(NTOT / 128, 1), 256, SMEM_BYTES>>>(xt, W2, b2, Ws, bs, out);
}

// round 7
// speedup vs baseline: 1.7713x; 1.7713x over previous
#include <cuda_runtime.h>
#include <cuda_fp16.h>
#include <mma.h>
#include <cstdint>

using namespace nvcuda;

// ---------------- problem constants ----------------
#define BATCH   8
#define NT      8192
#define NS      2048
#define NTOT    (BATCH * NT)      // 65536 target rows
#define C_TGT   128
#define C_SRC   256
#define C_IN    384
#define C_HID   256
#define C_OUT   128

// ---------------- device scratch (no allocs allowed) ----------------
__device__ __align__(128) int   g_knn_idx[NTOT * 3];
__device__ __align__(128) float g_knn_w  [NTOT * 3];
__device__ __align__(128) float g_interp [NTOT * C_SRC];   // 64 MB
__device__ __align__(128) float g_hidden [NTOT * C_HID];   // 64 MB

// ============================================================
// Kernel 1: brute-force 3-NN per target within its batch.
// ============================================================
__global__ __launch_bounds__(256)
void knn_kernel(const float* __restrict__ pos_t, const float* __restrict__ pos_s)
{
    __shared__ float4 sp[NS];             // 32 KB
    const int b    = blockIdx.x >> 5;
    const int tile = blockIdx.x & 31;

    const float* ps = pos_s + (size_t)b * NS * 3;
    for (int s = threadIdx.x; s < NS; s += 256) {
        sp[s] = make_float4(ps[3*s], ps[3*s+1], ps[3*s+2], 0.f);
    }
    __syncthreads();

    const int t = (b * 32 + tile) * 256 + threadIdx.x;
    const float tx = pos_t[3*t], ty = pos_t[3*t+1], tz = pos_t[3*t+2];

    float d0 = 1e30f, d1 = 1e30f, d2 = 1e30f;
    int   i0 = 0,     i1 = 0,     i2 = 0;

    #pragma unroll 4
    for (int s = 0; s < NS; ++s) {
        float4 p = sp[s];
        float dx = tx - p.x, dy = ty - p.y, dz = tz - p.z;
        float d  = fmaf(dz, dz, fmaf(dy, dy, dx * dx));
        if (d < d2) {
            if (d < d1) {
                d2 = d1; i2 = i1;
                if (d < d0) { d1 = d0; i1 = i0; d0 = d; i0 = s; }
                else        { d1 = d;  i1 = s; }
            } else { d2 = d; i2 = s; }
        }
    }

    const float w0 = 1.f / fmaxf(d0, 1e-16f);
    const float w1 = 1.f / fmaxf(d1, 1e-16f);
    const float w2 = 1.f / fmaxf(d2, 1e-16f);
    const float inv = 1.f / (w0 + w1 + w2);

    g_knn_w[3*t+0] = w0 * inv;
    g_knn_w[3*t+1] = w1 * inv;
    g_knn_w[3*t+2] = w2 * inv;
    g_knn_idx[3*t+0] = b * NS + i0;
    g_knn_idx[3*t+1] = b * NS + i1;
    g_knn_idx[3*t+2] = b * NS + i2;
}

// ============================================================
// Kernel 2: interpolation gather. One warp per target row.
// ============================================================
__global__ __launch_bounds__(256)
void interp_kernel(const float* __restrict__ xs)
{
    const int row  = blockIdx.x * 8 + (threadIdx.x >> 5);
    const int lane = threadIdx.x & 31;

    const int   i0 = g_knn_idx[3*row+0];
    const int   i1 = g_knn_idx[3*row+1];
    const int   i2 = g_knn_idx[3*row+2];
    const float w0 = g_knn_w[3*row+0];
    const float w1 = g_knn_w[3*row+1];
    const float w2 = g_knn_w[3*row+2];

    const float4* s0 = (const float4*)(xs + (size_t)i0 * C_SRC);
    const float4* s1 = (const float4*)(xs + (size_t)i1 * C_SRC);
    const float4* s2 = (const float4*)(xs + (size_t)i2 * C_SRC);
    float4* dst = (float4*)(g_interp + (size_t)row * C_SRC);

    #pragma unroll
    for (int h = 0; h < 2; ++h) {
        const int c = lane + h * 32;
        float4 a = s0[c], b = s1[c], d = s2[c];
        float4 r;
        r.x = w0*a.x + w1*b.x + w2*d.x;
        r.y = w0*a.y + w1*b.y + w2*d.y;
        r.z = w0*a.z + w1*b.z + w2*d.z;
        r.w = w0*a.w + w1*b.w + w2*d.w;
        dst[c] = r;
    }
}

// ============================================================
// fp16 GEMM machinery: 128x128 block tile, 8 warps (4x2), KC=16,
// wmma m16n16k16 half, register-pipelined LDG -> cvt -> STS staging.
// ============================================================
#define KC      16
#define SA_LD   24                    // halves per A row (16 + 8 pad)
#define SB_LD   144                   // halves per B row (128 + 16 pad)
#define SA_HSZ  (128 * SA_LD)         // 3072 halves
#define SB_HSZ  (KC * SB_LD)          // 2304 halves
#define STG_H   (SA_HSZ + SB_HSZ)     // 5376 halves / stage
#define SMEM_FLOATS 8192              // 32 KB: covers 2 half stages + fp32 epilogue

using FragA = wmma::fragment<wmma::matrix_a, 16, 16, 16, __half, wmma::row_major>;
using FragB = wmma::fragment<wmma::matrix_b, 16, 16, 16, __half, wmma::row_major>;
using FragC = wmma::fragment<wmma::accumulator, 16, 16, 16, float>;

// load one K=16 chunk into registers (A: 128x16, B: 16x128 fp32)
__device__ __forceinline__ void load_regs(
    float4 ra[2], float4 rb[2], int tid, int m0,
    const float* __restrict__ abase, int astride, int aoff,
    const float* __restrict__ bbase, int bstride, int boff, int n0)
{
    #pragma unroll
    for (int tI = 0; tI < 2; ++tI) {
        const int i4 = tid + tI * 256;        // 512 float4 (A)
        const int r  = i4 >> 2;               // 0..127
        const int c4 = (i4 & 3) << 2;         // 0,4,8,12
        ra[tI] = *(const float4*)(abase + (size_t)(m0 + r) * astride + aoff + c4);
    }
    #pragma unroll
    for (int tI = 0; tI < 2; ++tI) {
        const int i4 = tid + tI * 256;        // 512 float4 (B)
        const int r  = i4 >> 5;               // 0..15
        const int c4 = (i4 & 31) << 2;        // 0..124
        rb[tI] = *(const float4*)(bbase + (size_t)(boff + r) * bstride + n0 + c4);
    }
}

// convert to half and store one staged chunk
__device__ __forceinline__ void sts_regs(
    __half* sA, __half* sB, const float4 ra[2], const float4 rb[2], int tid)
{
    #pragma unroll
    for (int tI = 0; tI < 2; ++tI) {
        const int i4 = tid + tI * 256;
        const int r  = i4 >> 2;
        const int c4 = (i4 & 3) << 2;
        __half2* p = (__half2*)&sA[r * SA_LD + c4];
        p[0] = __floats2half2_rn(ra[tI].x, ra[tI].y);
        p[1] = __floats2half2_rn(ra[tI].z, ra[tI].w);
    }
    #pragma unroll
    for (int tI = 0; tI < 2; ++tI) {
        const int i4 = tid + tI * 256;
        const int r  = i4 >> 5;
        const int c4 = (i4 & 31) << 2;
        __half2* p = (__half2*)&sB[r * SB_LD + c4];
        p[0] = __floats2half2_rn(rb[tI].x, rb[tI].y);
        p[1] = __floats2half2_rn(rb[tI].z, rb[tI].w);
    }
}

// consume one staged K=16 chunk: 6 fragment loads + 8 mma per warp
__device__ __forceinline__ void compute_chunk(
    const __half* sA, const __half* sB, int warp_m, int warp_n, FragC fc[2][4])
{
    FragA fa[2];
    FragB fb[4];
    #pragma unroll
    for (int i = 0; i < 2; ++i)
        wmma::load_matrix_sync(fa[i], &sA[(warp_m*32 + i*16) * SA_LD], SA_LD);
    #pragma unroll
    for (int j = 0; j < 4; ++j)
        wmma::load_matrix_sync(fb[j], &sB[warp_n*64 + j*16], SB_LD);
    #pragma unroll
    for (int i = 0; i < 2; ++i)
        #pragma unroll
        for (int j = 0; j < 4; ++j)
            wmma::mma_sync(fc[i][j], fa[i], fb[j], fc[i][j]);
}

// ------------------------------------------------------------
// GEMM1: h = relu([x_target | interp] @ W1 + b1)   K=384, N=256
// ------------------------------------------------------------
__global__ __launch_bounds__(256, 2)
void gemm1_kernel(const float* __restrict__ xt,
                  const float* __restrict__ W1,
                  const float* __restrict__ b1)
{
    __shared__ __align__(16) float smemf[SMEM_FLOATS];
    __half* sh = (__half*)smemf;

    const int m0 = blockIdx.x * 128;
    const int n0 = blockIdx.y * 128;
    const int tid = threadIdx.x;
    const int w   = tid >> 5;
    const int warp_m = w & 3;
    const int warp_n = w >> 2;
    const int lane = tid & 31;

    FragC fc[2][4];
    #pragma unroll
    for (int i = 0; i < 2; ++i)
        #pragma unroll
        for (int j = 0; j < 4; ++j)
            wmma::fill_fragment(fc[i][j], 0.f);

    auto asrc = [&](int kc, const float*& ab, int& as, int& ao) {
        if (kc < C_TGT) { ab = xt;       as = C_TGT; ao = kc;         }
        else            { ab = g_interp; as = C_SRC; ao = kc - C_TGT; }
    };

    float4 ra[2], rb[2];
    {   // prologue: chunk 0 -> regs
        const float* ab; int as, ao;
        asrc(0, ab, as, ao);
        load_regs(ra, rb, tid, m0, ab, as, ao, W1, C_HID, 0, n0);
    }

    const int NITER = C_IN / KC;   // 24
    for (int it = 0; it < NITER; ++it) {
        __half* st = sh + (it & 1) * STG_H;
        sts_regs(st, st + SA_HSZ, ra, rb, tid);
        __syncthreads();
        if (it + 1 < NITER) {       // issue next LDGs; latency hidden by compute
            const int kc = (it + 1) * KC;
            const float* ab; int as, ao;
            asrc(kc, ab, as, ao);
            load_regs(ra, rb, tid, m0, ab, as, ao, W1, C_HID, kc, n0);
        }
        compute_chunk(st, st + SA_HSZ, warp_m, warp_n, fc);
    }
    __syncthreads();

    // epilogue: bias + relu -> g_hidden (smem reused as fp32 staging)
    float* wb = &smemf[w * 1024];
    const int gm_base = m0 + warp_m * 32;
    const int gn_base = n0 + warp_n * 64;
    #pragma unroll
    for (int i = 0; i < 2; ++i) {
        #pragma unroll
        for (int j = 0; j < 4; ++j)
            wmma::store_matrix_sync(wb + j*16, fc[i][j], 64, wmma::mem_row_major);
        __syncwarp();
        #pragma unroll
        for (int e = lane; e < 256; e += 32) {
            const int rr = e >> 4;
            const int cc = (e & 15) << 2;
            float4 v = *(float4*)(wb + rr*64 + cc);
            const int gn = gn_base + cc;
            v.x = fmaxf(v.x + b1[gn+0], 0.f);
            v.y = fmaxf(v.y + b1[gn+1], 0.f);
            v.z = fmaxf(v.z + b1[gn+2], 0.f);
            v.w = fmaxf(v.w + b1[gn+3], 0.f);
            *(float4*)(&g_hidden[(size_t)(gm_base + i*16 + rr) * C_HID + gn]) = v;
        }
        __syncwarp();
    }
}

// ------------------------------------------------------------
// GEMM2: out = relu([h | x_target | interp] @ [W2; Ws] + (b2+bs))
// K=640, N=128
// ------------------------------------------------------------
__global__ __launch_bounds__(256, 2)
void gemm2_kernel(const float* __restrict__ xt,
                  const float* __restrict__ W2,
                  const float* __restrict__ b2,
                  const float* __restrict__ Ws,
                  const float* __restrict__ bs,
                  float* __restrict__ out)
{
    __shared__ __align__(16) float smemf[SMEM_FLOATS];
    __half* sh = (__half*)smemf;

    const int m0 = blockIdx.x * 128;
    const int tid = threadIdx.x;
    const int w   = tid >> 5;
    const int warp_m = w & 3;
    const int warp_n = w >> 2;
    const int lane = tid & 31;

    FragC fc[2][4];
    #pragma unroll
    for (int i = 0; i < 2; ++i)
        #pragma unroll
        for (int j = 0; j < 4; ++j)
            wmma::fill_fragment(fc[i][j], 0.f);

    auto srcs = [&](int kc, const float*& ab, int& as, int& ao,
                    const float*& bb, int& bo) {
        if      (kc < 256) { ab = g_hidden; as = C_HID; ao = kc;       }
        else if (kc < 384) { ab = xt;       as = C_TGT; ao = kc - 256; }
        else               { ab = g_interp; as = C_SRC; ao = kc - 384; }
        if (kc < 256) { bb = W2; bo = kc;       }
        else          { bb = Ws; bo = kc - 256; }
    };

    float4 ra[2], rb[2];
    {
        const float* ab; const float* bb; int as, ao, bo;
        srcs(0, ab, as, ao, bb, bo);
        load_regs(ra, rb, tid, m0, ab, as, ao, bb, C_OUT, bo, 0);
    }

    const int NITER = 640 / KC;   // 40
    for (int it = 0; it < NITER; ++it) {
        __half* st = sh + (it & 1) * STG_H;
        sts_regs(st, st + SA_HSZ, ra, rb, tid);
        __syncthreads();
        if (it + 1 < NITER) {
            const int kc = (it + 1) * KC;
            const float* ab; const float* bb; int as, ao, bo;
            srcs(kc, ab, as, ao, bb, bo);
            load_regs(ra, rb, tid, m0, ab, as, ao, bb, C_OUT, bo, 0);
        }
        compute_chunk(st, st + SA_HSZ, warp_m, warp_n, fc);
    }
    __syncthreads();

    // epilogue: (b2+bs) + relu -> out
    float* wb = &smemf[w * 1024];
    const int gm_base = m0 + warp_m * 32;
    const int gn_base = warp_n * 64;
    #pragma unroll
    for (int i = 0; i < 2; ++i) {
        #pragma unroll
        for (int j = 0; j < 4; ++j)
            wmma::store_matrix_sync(wb + j*16, fc[i][j], 64, wmma::mem_row_major);
        __syncwarp();
        #pragma unroll
        for (int e = lane; e < 256; e += 32) {
            const int rr = e >> 4;
            const int cc = (e & 15) << 2;
            float4 v = *(float4*)(wb + rr*64 + cc);
            const int gn = gn_base + cc;
            v.x = fmaxf(v.x + b2[gn+0] + bs[gn+0], 0.f);
            v.y = fmaxf(v.y + b2[gn+1] + bs[gn+1], 0.f);
            v.z = fmaxf(v.z + b2[gn+2] + bs[gn+2], 0.f);
            v.w = fmaxf(v.w + b2[gn+3] + bs[gn+3], 0.f);
            *(float4*)(&out[(size_t)(gm_base + i*16 + rr) * C_OUT + gn]) = v;
        }
        __syncwarp();
    }
}

// ============================================================
// Launch.
// ============================================================
extern "C" void kernel_launch(void* const* d_in, const int* in_sizes, int n_in,
                              void* d_out, int out_size)
{
    const float* xt = (const float*)d_in[0];
    const float* pt = (const float*)d_in[1];
    const float* xs = (const float*)d_in[3];
    const float* ps = (const float*)d_in[4];
    const float* W1 = (const float*)d_in[6];
    const float* b1 = (const float*)d_in[7];
    const float* W2 = (const float*)d_in[8];
    const float* b2 = (const float*)d_in[9];
    const float* Ws = (const float*)d_in[10];
    const float* bs = (const float*)d_in[11];
    float* out = (float*)d_out;

    knn_kernel   <<<BATCH * (NT / 256), 256>>>(pt, ps);
    interp_kernel<<<NTOT / 8, 256>>>(xs);
    gemm1_kernel <<<dim3(NTOT / 128, C_HID / 128), 256>>>(xt, W1, b1);
    gemm2_kernel <<<dim3(NTOT / 128, 1), 256>>>(xt, W2, b2, Ws, bs, out);
}

// round 8
// speedup vs baseline: 2.2451x; 1.2675x over previous
#include <cuda_runtime.h>
#include <cuda_fp16.h>
#include <mma.h>
#include <cstdint>

using namespace nvcuda;

// ---------------- problem constants ----------------
#define BATCH   8
#define NT      8192
#define NS      2048
#define NTOT    (BATCH * NT)      // 65536 target rows
#define C_TGT   128
#define C_SRC   256
#define C_IN    384
#define C_HID   256
#define C_OUT   128

// ---------------- device scratch (no allocs allowed) ----------------
__device__ __align__(128) int    g_knn_idx[NTOT * 3];
__device__ __align__(128) float  g_knn_w  [NTOT * 3];
__device__ __align__(128) __half g_interp_h[NTOT * C_SRC];   // 32 MB
__device__ __align__(128) __half g_hidden_h[NTOT * C_HID];   // 32 MB
__device__ __align__(128) __half g_xt_h   [NTOT * C_TGT];    // 16 MB
__device__ __align__(128) __half g_W1_h   [C_IN * C_HID];
__device__ __align__(128) __half g_Wcat_h [(C_HID + C_IN) * C_OUT];  // [W2;Ws] 640x128
__device__ __align__(128) float  g_bcat   [C_OUT];                   // b2+bs

// ============================================================
// cp.async helpers
// ============================================================
__device__ __forceinline__ void cp16h(__half* dst_smem, const __half* src_gmem) {
    uint32_t d = (uint32_t)__cvta_generic_to_shared(dst_smem);
    asm volatile("cp.async.cg.shared.global [%0], [%1], 16;\n" :: "r"(d), "l"(src_gmem));
}
__device__ __forceinline__ void cp_commit() {
    asm volatile("cp.async.commit_group;\n");
}
template<int N>
__device__ __forceinline__ void cp_wait() {
    asm volatile("cp.async.wait_group %0;\n" :: "n"(N));
}

// ============================================================
// Convert kernels (run once per launch; tiny)
// ============================================================
__global__ __launch_bounds__(256)
void cvt_xt_kernel(const float* __restrict__ xt)
{
    const int i4 = blockIdx.x * 256 + threadIdx.x;     // float4 index
    float4 v = ((const float4*)xt)[i4];
    __half2* p = (__half2*)&g_xt_h[i4 * 4];
    p[0] = __floats2half2_rn(v.x, v.y);
    p[1] = __floats2half2_rn(v.z, v.w);
}

__global__ __launch_bounds__(256)
void cvt_weights_kernel(const float* __restrict__ W1,
                        const float* __restrict__ W2,
                        const float* __restrict__ Ws,
                        const float* __restrict__ b2,
                        const float* __restrict__ bs)
{
    const int i = blockIdx.x * 256 + threadIdx.x;
    if (i < C_IN * C_HID)            g_W1_h[i] = __float2half_rn(W1[i]);
    if (i < C_HID * C_OUT)           g_Wcat_h[i] = __float2half_rn(W2[i]);
    if (i < C_IN * C_OUT)            g_Wcat_h[C_HID * C_OUT + i] = __float2half_rn(Ws[i]);
    if (i < C_OUT)                   g_bcat[i] = b2[i] + bs[i];
}

// ============================================================
// Kernel 1: brute-force 3-NN per target within its batch.
// ============================================================
__global__ __launch_bounds__(256)
void knn_kernel(const float* __restrict__ pos_t, const float* __restrict__ pos_s)
{
    __shared__ float4 sp[NS];             // 32 KB
    const int b    = blockIdx.x >> 5;
    const int tile = blockIdx.x & 31;

    const float* ps = pos_s + (size_t)b * NS * 3;
    for (int s = threadIdx.x; s < NS; s += 256) {
        sp[s] = make_float4(ps[3*s], ps[3*s+1], ps[3*s+2], 0.f);
    }
    __syncthreads();

    const int t = (b * 32 + tile) * 256 + threadIdx.x;
    const float tx = pos_t[3*t], ty = pos_t[3*t+1], tz = pos_t[3*t+2];

    float d0 = 1e30f, d1 = 1e30f, d2 = 1e30f;
    int   i0 = 0,     i1 = 0,     i2 = 0;

    #pragma unroll 4
    for (int s = 0; s < NS; ++s) {
        float4 p = sp[s];
        float dx = tx - p.x, dy = ty - p.y, dz = tz - p.z;
        float d  = fmaf(dz, dz, fmaf(dy, dy, dx * dx));
        if (d < d2) {
            if (d < d1) {
                d2 = d1; i2 = i1;
                if (d < d0) { d1 = d0; i1 = i0; d0 = d; i0 = s; }
                else        { d1 = d;  i1 = s; }
            } else { d2 = d; i2 = s; }
        }
    }

    const float w0 = 1.f / fmaxf(d0, 1e-16f);
    const float w1 = 1.f / fmaxf(d1, 1e-16f);
    const float w2 = 1.f / fmaxf(d2, 1e-16f);
    const float inv = 1.f / (w0 + w1 + w2);

    g_knn_w[3*t+0] = w0 * inv;
    g_knn_w[3*t+1] = w1 * inv;
    g_knn_w[3*t+2] = w2 * inv;
    g_knn_idx[3*t+0] = b * NS + i0;
    g_knn_idx[3*t+1] = b * NS + i1;
    g_knn_idx[3*t+2] = b * NS + i2;
}

// ============================================================
// Kernel 2: interpolation gather -> half output.
// ============================================================
__global__ __launch_bounds__(256)
void interp_kernel(const float* __restrict__ xs)
{
    const int row  = blockIdx.x * 8 + (threadIdx.x >> 5);
    const int lane = threadIdx.x & 31;

    const int   i0 = g_knn_idx[3*row+0];
    const int   i1 = g_knn_idx[3*row+1];
    const int   i2 = g_knn_idx[3*row+2];
    const float w0 = g_knn_w[3*row+0];
    const float w1 = g_knn_w[3*row+1];
    const float w2 = g_knn_w[3*row+2];

    const float4* s0 = (const float4*)(xs + (size_t)i0 * C_SRC);
    const float4* s1 = (const float4*)(xs + (size_t)i1 * C_SRC);
    const float4* s2 = (const float4*)(xs + (size_t)i2 * C_SRC);
    __half2* dst = (__half2*)&g_interp_h[(size_t)row * C_SRC];

    #pragma unroll
    for (int h = 0; h < 2; ++h) {
        const int c = lane + h * 32;          // float4 index, 64/row
        float4 a = s0[c], b = s1[c], d = s2[c];
        float rx = w0*a.x + w1*b.x + w2*d.x;
        float ry = w0*a.y + w1*b.y + w2*d.y;
        float rz = w0*a.z + w1*b.z + w2*d.z;
        float rw = w0*a.w + w1*b.w + w2*d.w;
        dst[c*2+0] = __floats2half2_rn(rx, ry);
        dst[c*2+1] = __floats2half2_rn(rz, rw);
    }
}

// ============================================================
// half GEMM: 128x128 tile, 8 warps (4x2), KC=32, cp.async 3-stage.
// ============================================================
#define KC      32
#define PIPE    3
#define SA_LD   40                      // halves/row (32 + 8 pad)
#define SB_LD   136                     // halves/row (128 + 8 pad)
#define SA_HSZ  (128 * SA_LD)           // 5120
#define SB_HSZ  (KC * SB_LD)            // 4352
#define STG_H   (SA_HSZ + SB_HSZ)       // 9472 halves / stage
#define SMEM_BYTES (PIPE * STG_H * 2)   // 56832 B

using FragA = wmma::fragment<wmma::matrix_a, 16, 16, 16, __half, wmma::row_major>;
using FragB = wmma::fragment<wmma::matrix_b, 16, 16, 16, __half, wmma::row_major>;
using FragC = wmma::fragment<wmma::accumulator, 16, 16, 16, float>;

// stage A(128xKC) + B(KCx128) half tiles via cp.async
__device__ __forceinline__ void stage_tiles(
    __half* sA, __half* sB, int tid, int m0,
    const __half* __restrict__ abase, int astride, int aoff,
    const __half* __restrict__ bbase, int bstride, int boff, int n0)
{
    #pragma unroll
    for (int tI = 0; tI < 2; ++tI) {
        const int i = tid + tI * 256;          // 512 chunks of 8 halves
        const int r  = i >> 2;                 // 0..127
        const int c8 = (i & 3) << 3;           // 0,8,16,24
        cp16h(&sA[r * SA_LD + c8], abase + (size_t)(m0 + r) * astride + aoff + c8);
    }
    #pragma unroll
    for (int tI = 0; tI < 2; ++tI) {
        const int i = tid + tI * 256;
        const int r  = i >> 4;                 // 0..31
        const int c8 = (i & 15) << 3;          // 0..120
        cp16h(&sB[r * SB_LD + c8], bbase + (size_t)(boff + r) * bstride + n0 + c8);
    }
}

// consume one KC=32 chunk: 2 x (6 frag loads + 8 mma) per warp
__device__ __forceinline__ void compute_chunk(
    const __half* sA, const __half* sB, int warp_m, int warp_n, FragC fc[2][4])
{
    #pragma unroll
    for (int k16 = 0; k16 < KC; k16 += 16) {
        FragA fa[2];
        FragB fb[4];
        #pragma unroll
        for (int i = 0; i < 2; ++i)
            wmma::load_matrix_sync(fa[i], &sA[(warp_m*32 + i*16) * SA_LD + k16], SA_LD);
        #pragma unroll
        for (int j = 0; j < 4; ++j)
            wmma::load_matrix_sync(fb[j], &sB[k16 * SB_LD + warp_n*64 + j*16], SB_LD);
        #pragma unroll
        for (int i = 0; i < 2; ++i)
            #pragma unroll
            for (int j = 0; j < 4; ++j)
                wmma::mma_sync(fc[i][j], fa[i], fb[j], fc[i][j]);
    }
}

// ------------------------------------------------------------
// GEMM1: hidden = relu([xt | interp] @ W1 + b1)  K=384, N=256 -> half
// ------------------------------------------------------------
__global__ __launch_bounds__(256, 2)
void gemm1_kernel(const float* __restrict__ b1)
{
    extern __shared__ __align__(16) __half sh[];
    const int m0 = blockIdx.x * 128;
    const int n0 = blockIdx.y * 128;
    const int tid = threadIdx.x;
    const int w   = tid >> 5;
    const int warp_m = w & 3;
    const int warp_n = w >> 2;
    const int lane = tid & 31;

    FragC fc[2][4];
    #pragma unroll
    for (int i = 0; i < 2; ++i)
        #pragma unroll
        for (int j = 0; j < 4; ++j)
            wmma::fill_fragment(fc[i][j], 0.f);

    auto stage_it = [&](int it) {
        const int kc = it * KC;
        const __half* ab; int as, ao;
        if (kc < C_TGT) { ab = g_xt_h;     as = C_TGT; ao = kc;         }
        else            { ab = g_interp_h; as = C_SRC; ao = kc - C_TGT; }
        __half* st = sh + (it % PIPE) * STG_H;
        stage_tiles(st, st + SA_HSZ, tid, m0, ab, as, ao, g_W1_h, C_HID, kc, n0);
        cp_commit();
    };

    const int NITER = C_IN / KC;   // 12
    stage_it(0);
    stage_it(1);

    for (int it = 0; it < NITER; ++it) {
        cp_wait<1>();
        __syncthreads();
        if (it + 2 < NITER) stage_it(it + 2);
        const __half* st = sh + (it % PIPE) * STG_H;
        compute_chunk(st, st + SA_HSZ, warp_m, warp_n, fc);
    }
    __syncthreads();

    // epilogue: bias + relu -> half hidden
    float* wb = (float*)sh + w * 1024;
    const int gm_base = m0 + warp_m * 32;
    const int gn_base = n0 + warp_n * 64;
    #pragma unroll
    for (int i = 0; i < 2; ++i) {
        #pragma unroll
        for (int j = 0; j < 4; ++j)
            wmma::store_matrix_sync(wb + j*16, fc[i][j], 64, wmma::mem_row_major);
        __syncwarp();
        #pragma unroll
        for (int e = lane; e < 256; e += 32) {
            const int rr = e >> 4;
            const int cc = (e & 15) << 2;
            float4 v = *(float4*)(wb + rr*64 + cc);
            const int gn = gn_base + cc;
            v.x = fmaxf(v.x + b1[gn+0], 0.f);
            v.y = fmaxf(v.y + b1[gn+1], 0.f);
            v.z = fmaxf(v.z + b1[gn+2], 0.f);
            v.w = fmaxf(v.w + b1[gn+3], 0.f);
            __half2 h01 = __floats2half2_rn(v.x, v.y);
            __half2 h23 = __floats2half2_rn(v.z, v.w);
            __half2* p = (__half2*)&g_hidden_h[(size_t)(gm_base + i*16 + rr) * C_HID + gn];
            p[0] = h01; p[1] = h23;
        }
        __syncwarp();
    }
}

// ------------------------------------------------------------
// GEMM2: out = relu([hidden | xt | interp] @ Wcat + bcat)  K=640, N=128
// ------------------------------------------------------------
__global__ __launch_bounds__(256, 2)
void gemm2_kernel(float* __restrict__ out)
{
    extern __shared__ __align__(16) __half sh[];
    const int m0 = blockIdx.x * 128;
    const int tid = threadIdx.x;
    const int w   = tid >> 5;
    const int warp_m = w & 3;
    const int warp_n = w >> 2;
    const int lane = tid & 31;

    FragC fc[2][4];
    #pragma unroll
    for (int i = 0; i < 2; ++i)
        #pragma unroll
        for (int j = 0; j < 4; ++j)
            wmma::fill_fragment(fc[i][j], 0.f);

    auto stage_it = [&](int it) {
        const int kc = it * KC;
        const __half* ab; int as, ao;
        if      (kc < 256) { ab = g_hidden_h; as = C_HID; ao = kc;       }
        else if (kc < 384) { ab = g_xt_h;     as = C_TGT; ao = kc - 256; }
        else               { ab = g_interp_h; as = C_SRC; ao = kc - 384; }
        __half* st = sh + (it % PIPE) * STG_H;
        stage_tiles(st, st + SA_HSZ, tid, m0, ab, as, ao, g_Wcat_h, C_OUT, kc, 0);
        cp_commit();
    };

    const int NITER = (C_HID + C_IN) / KC;   // 20
    stage_it(0);
    stage_it(1);

    for (int it = 0; it < NITER; ++it) {
        cp_wait<1>();
        __syncthreads();
        if (it + 2 < NITER) stage_it(it + 2);
        const __half* st = sh + (it % PIPE) * STG_H;
        compute_chunk(st, st + SA_HSZ, warp_m, warp_n, fc);
    }
    __syncthreads();

    // epilogue: bcat + relu -> fp32 out
    float* wb = (float*)sh + w * 1024;
    const int gm_base = m0 + warp_m * 32;
    const int gn_base = warp_n * 64;
    #pragma unroll
    for (int i = 0; i < 2; ++i) {
        #pragma unroll
        for (int j = 0; j < 4; ++j)
            wmma::store_matrix_sync(wb + j*16, fc[i][j], 64, wmma::mem_row_major);
        __syncwarp();
        #pragma unroll
        for (int e = lane; e < 256; e += 32) {
            const int rr = e >> 4;
            const int cc = (e & 15) << 2;
            float4 v = *(float4*)(wb + rr*64 + cc);
            const int gn = gn_base + cc;
            v.x = fmaxf(v.x + g_bcat[gn+0], 0.f);
            v.y = fmaxf(v.y + g_bcat[gn+1], 0.f);
            v.z = fmaxf(v.z + g_bcat[gn+2], 0.f);
            v.w = fmaxf(v.w + g_bcat[gn+3], 0.f);
            *(float4*)(&out[(size_t)(gm_base + i*16 + rr) * C_OUT + gn]) = v;
        }
        __syncwarp();
    }
}

// ============================================================
// Launch.
// ============================================================
extern "C" void kernel_launch(void* const* d_in, const int* in_sizes, int n_in,
                              void* d_out, int out_size)
{
    const float* xt = (const float*)d_in[0];
    const float* pt = (const float*)d_in[1];
    const float* xs = (const float*)d_in[3];
    const float* ps = (const float*)d_in[4];
    const float* W1 = (const float*)d_in[6];
    const float* b1 = (const float*)d_in[7];
    const float* W2 = (const float*)d_in[8];
    const float* b2 = (const float*)d_in[9];
    const float* Ws = (const float*)d_in[10];
    const float* bs = (const float*)d_in[11];
    float* out = (float*)d_out;

    cudaFuncSetAttribute(gemm1_kernel, cudaFuncAttributeMaxDynamicSharedMemorySize, SMEM_BYTES);
    cudaFuncSetAttribute(gemm2_kernel, cudaFuncAttributeMaxDynamicSharedMemorySize, SMEM_BYTES);

    cvt_xt_kernel     <<<NTOT * C_TGT / 4 / 256, 256>>>(xt);
    cvt_weights_kernel<<<(C_IN * C_HID + 255) / 256, 256>>>(W1, W2, Ws, b2, bs);
    knn_kernel        <<<BATCH * (NT / 256), 256>>>(pt, ps);
    interp_kernel     <<<NTOT / 8, 256>>>(xs);
    gemm1_kernel      <<<dim3(NTOT / 128, C_HID / 128), 256, SMEM_BYTES>>>(b1);
    gemm2_kernel      <<<dim3(NTOT / 128, 1), 256, SMEM_BYTES>>>(out);
}

// round 9
// speedup vs baseline: 2.2621x; 1.0076x over previous
#include <cuda_runtime.h>
#include <cuda_fp16.h>
#include <mma.h>
#include <cstdint>

using namespace nvcuda;

// ---------------- problem constants ----------------
#define BATCH   8
#define NT      8192
#define NS      2048
#define NTOT    (BATCH * NT)      // 65536 target rows
#define C_TGT   128
#define C_SRC   256
#define C_IN    384
#define C_HID   256
#define C_OUT   128

// ---------------- device scratch (no allocs allowed) ----------------
__device__ __align__(128) int    g_knn_idx[NTOT * 3];
__device__ __align__(128) float  g_knn_w  [NTOT * 3];
__device__ __align__(128) __half g_interp_h[NTOT * C_SRC];   // 32 MB
__device__ __align__(128) __half g_hidden_h[NTOT * C_HID];   // 32 MB
__device__ __align__(128) __half g_xt_h   [NTOT * C_TGT];    // 16 MB
__device__ __align__(128) __half g_W1_h   [C_IN * C_HID];
__device__ __align__(128) __half g_Wcat_h [(C_HID + C_IN) * C_OUT];  // [W2;Ws] 640x128
__device__ __align__(128) float  g_bcat   [C_OUT];                   // b2+bs

// ============================================================
// cp.async helpers
// ============================================================
__device__ __forceinline__ void cp16h(__half* dst_smem, const __half* src_gmem) {
    uint32_t d = (uint32_t)__cvta_generic_to_shared(dst_smem);
    asm volatile("cp.async.cg.shared.global [%0], [%1], 16;\n" :: "r"(d), "l"(src_gmem));
}
__device__ __forceinline__ void cp_commit() {
    asm volatile("cp.async.commit_group;\n");
}
template<int N>
__device__ __forceinline__ void cp_wait() {
    asm volatile("cp.async.wait_group %0;\n" :: "n"(N));
}

// ============================================================
// Convert kernels (run once per launch; tiny)
// ============================================================
__global__ __launch_bounds__(256)
void cvt_xt_kernel(const float* __restrict__ xt)
{
    const int i4 = blockIdx.x * 256 + threadIdx.x;     // float4 index
    float4 v = ((const float4*)xt)[i4];
    __half2* p = (__half2*)&g_xt_h[i4 * 4];
    p[0] = __floats2half2_rn(v.x, v.y);
    p[1] = __floats2half2_rn(v.z, v.w);
}

__global__ __launch_bounds__(256)
void cvt_weights_kernel(const float* __restrict__ W1,
                        const float* __restrict__ W2,
                        const float* __restrict__ Ws,
                        const float* __restrict__ b2,
                        const float* __restrict__ bs)
{
    const int i = blockIdx.x * 256 + threadIdx.x;
    if (i < C_IN * C_HID)            g_W1_h[i] = __float2half_rn(W1[i]);
    if (i < C_HID * C_OUT)           g_Wcat_h[i] = __float2half_rn(W2[i]);
    if (i < C_IN * C_OUT)            g_Wcat_h[C_HID * C_OUT + i] = __float2half_rn(Ws[i]);
    if (i < C_OUT)                   g_bcat[i] = b2[i] + bs[i];
}

// ============================================================
// Kernel 1: brute-force 3-NN per target within its batch.
// ============================================================
__global__ __launch_bounds__(256)
void knn_kernel(const float* __restrict__ pos_t, const float* __restrict__ pos_s)
{
    __shared__ float4 sp[NS];             // 32 KB
    const int b    = blockIdx.x >> 5;
    const int tile = blockIdx.x & 31;

    const float* ps = pos_s + (size_t)b * NS * 3;
    for (int s = threadIdx.x; s < NS; s += 256) {
        sp[s] = make_float4(ps[3*s], ps[3*s+1], ps[3*s+2], 0.f);
    }
    __syncthreads();

    const int t = (b * 32 + tile) * 256 + threadIdx.x;
    const float tx = pos_t[3*t], ty = pos_t[3*t+1], tz = pos_t[3*t+2];

    float d0 = 1e30f, d1 = 1e30f, d2 = 1e30f;
    int   i0 = 0,     i1 = 0,     i2 = 0;

    #pragma unroll 4
    for (int s = 0; s < NS; ++s) {
        float4 p = sp[s];
        float dx = tx - p.x, dy = ty - p.y, dz = tz - p.z;
        float d  = fmaf(dz, dz, fmaf(dy, dy, dx * dx));
        if (d < d2) {
            if (d < d1) {
                d2 = d1; i2 = i1;
                if (d < d0) { d1 = d0; i1 = i0; d0 = d; i0 = s; }
                else        { d1 = d;  i1 = s; }
            } else { d2 = d; i2 = s; }
        }
    }

    const float w0 = 1.f / fmaxf(d0, 1e-16f);
    const float w1 = 1.f / fmaxf(d1, 1e-16f);
    const float w2 = 1.f / fmaxf(d2, 1e-16f);
    const float inv = 1.f / (w0 + w1 + w2);

    g_knn_w[3*t+0] = w0 * inv;
    g_knn_w[3*t+1] = w1 * inv;
    g_knn_w[3*t+2] = w2 * inv;
    g_knn_idx[3*t+0] = b * NS + i0;
    g_knn_idx[3*t+1] = b * NS + i1;
    g_knn_idx[3*t+2] = b * NS + i2;
}

// ============================================================
// Kernel 2: interpolation gather -> half output.
// ============================================================
__global__ __launch_bounds__(256)
void interp_kernel(const float* __restrict__ xs)
{
    const int row  = blockIdx.x * 8 + (threadIdx.x >> 5);
    const int lane = threadIdx.x & 31;

    const int   i0 = g_knn_idx[3*row+0];
    const int   i1 = g_knn_idx[3*row+1];
    const int   i2 = g_knn_idx[3*row+2];
    const float w0 = g_knn_w[3*row+0];
    const float w1 = g_knn_w[3*row+1];
    const float w2 = g_knn_w[3*row+2];

    const float4* s0 = (const float4*)(xs + (size_t)i0 * C_SRC);
    const float4* s1 = (const float4*)(xs + (size_t)i1 * C_SRC);
    const float4* s2 = (const float4*)(xs + (size_t)i2 * C_SRC);
    __half2* dst = (__half2*)&g_interp_h[(size_t)row * C_SRC];

    #pragma unroll
    for (int h = 0; h < 2; ++h) {
        const int c = lane + h * 32;          // float4 index, 64/row
        float4 a = s0[c], b = s1[c], d = s2[c];
        float rx = w0*a.x + w1*b.x + w2*d.x;
        float ry = w0*a.y + w1*b.y + w2*d.y;
        float rz = w0*a.z + w1*b.z + w2*d.z;
        float rw = w0*a.w + w1*b.w + w2*d.w;
        dst[c*2+0] = __floats2half2_rn(rx, ry);
        dst[c*2+1] = __floats2half2_rn(rz, rw);
    }
}

// ============================================================
// half GEMM: 128x128 tile, 8 warps (4x2), KC=32, cp.async 3-stage.
// ============================================================
#define KC      32
#define PIPE    3
#define SA_LD   40                      // halves/row (32 + 8 pad)
#define SB_LD   136                     // halves/row (128 + 8 pad)
#define SA_HSZ  (128 * SA_LD)           // 5120
#define SB_HSZ  (KC * SB_LD)            // 4352
#define STG_H   (SA_HSZ + SB_HSZ)       // 9472 halves / stage
#define SMEM_BYTES (PIPE * STG_H * 2)   // 56832 B

using FragA = wmma::fragment<wmma::matrix_a, 16, 16, 16, __half, wmma::row_major>;
using FragB = wmma::fragment<wmma::matrix_b, 16, 16, 16, __half, wmma::row_major>;
using FragC = wmma::fragment<wmma::accumulator, 16, 16, 16, float>;

// stage A(128xKC) + B(KCx128) half tiles via cp.async
__device__ __forceinline__ void stage_tiles(
    __half* sA, __half* sB, int tid, int m0,
    const __half* __restrict__ abase, int astride, int aoff,
    const __half* __restrict__ bbase, int bstride, int boff, int n0)
{
    #pragma unroll
    for (int tI = 0; tI < 2; ++tI) {
        const int i = tid + tI * 256;          // 512 chunks of 8 halves
        const int r  = i >> 2;                 // 0..127
        const int c8 = (i & 3) << 3;           // 0,8,16,24
        cp16h(&sA[r * SA_LD + c8], abase + (size_t)(m0 + r) * astride + aoff + c8);
    }
    #pragma unroll
    for (int tI = 0; tI < 2; ++tI) {
        const int i = tid + tI * 256;
        const int r  = i >> 4;                 // 0..31
        const int c8 = (i & 15) << 3;          // 0..120
        cp16h(&sB[r * SB_LD + c8], bbase + (size_t)(boff + r) * bstride + n0 + c8);
    }
}

// consume one KC=32 chunk: 2 x (6 frag loads + 8 mma) per warp
__device__ __forceinline__ void compute_chunk(
    const __half* sA, const __half* sB, int warp_m, int warp_n, FragC fc[2][4])
{
    #pragma unroll
    for (int k16 = 0; k16 < KC; k16 += 16) {
        FragA fa[2];
        FragB fb[4];
        #pragma unroll
        for (int i = 0; i < 2; ++i)
            wmma::load_matrix_sync(fa[i], &sA[(warp_m*32 + i*16) * SA_LD + k16], SA_LD);
        #pragma unroll
        for (int j = 0; j < 4; ++j)
            wmma::load_matrix_sync(fb[j], &sB[k16 * SB_LD + warp_n*64 + j*16], SB_LD);
        #pragma unroll
        for (int i = 0; i < 2; ++i)
            #pragma unroll
            for (int j = 0; j < 4; ++j)
                wmma::mma_sync(fc[i][j], fa[i], fb[j], fc[i][j]);
    }
}

// ------------------------------------------------------------
// GEMM1: hidden = relu([xt | interp] @ W1 + b1)  K=384, N=256 -> half
// ------------------------------------------------------------
__global__ __launch_bounds__(256, 2)
void gemm1_kernel(const float* __restrict__ b1)
{
    extern __shared__ __align__(16) __half sh[];
    const int m0 = blockIdx.x * 128;
    const int n0 = blockIdx.y * 128;
    const int tid = threadIdx.x;
    const int w   = tid >> 5;
    const int warp_m = w & 3;
    const int warp_n = w >> 2;
    const int lane = tid & 31;

    FragC fc[2][4];
    #pragma unroll
    for (int i = 0; i < 2; ++i)
        #pragma unroll
        for (int j = 0; j < 4; ++j)
            wmma::fill_fragment(fc[i][j], 0.f);

    auto stage_it = [&](int it) {
        const int kc = it * KC;
        const __half* ab; int as, ao;
        if (kc < C_TGT) { ab = g_xt_h;     as = C_TGT; ao = kc;         }
        else            { ab = g_interp_h; as = C_SRC; ao = kc - C_TGT; }
        __half* st = sh + (it % PIPE) * STG_H;
        stage_tiles(st, st + SA_HSZ, tid, m0, ab, as, ao, g_W1_h, C_HID, kc, n0);
        cp_commit();
    };

    const int NITER = C_IN / KC;   // 12
    stage_it(0);
    stage_it(1);

    for (int it = 0; it < NITER; ++it) {
        cp_wait<1>();
        __syncthreads();
        if (it + 2 < NITER) stage_it(it + 2);
        const __half* st = sh + (it % PIPE) * STG_H;
        compute_chunk(st, st + SA_HSZ, warp_m, warp_n, fc);
    }
    __syncthreads();

    // epilogue: bias + relu -> half hidden
    float* wb = (float*)sh + w * 1024;
    const int gm_base = m0 + warp_m * 32;
    const int gn_base = n0 + warp_n * 64;
    #pragma unroll
    for (int i = 0; i < 2; ++i) {
        #pragma unroll
        for (int j = 0; j < 4; ++j)
            wmma::store_matrix_sync(wb + j*16, fc[i][j], 64, wmma::mem_row_major);
        __syncwarp();
        #pragma unroll
        for (int e = lane; e < 256; e += 32) {
            const int rr = e >> 4;
            const int cc = (e & 15) << 2;
            float4 v = *(float4*)(wb + rr*64 + cc);
            const int gn = gn_base + cc;
            v.x = fmaxf(v.x + b1[gn+0], 0.f);
            v.y = fmaxf(v.y + b1[gn+1], 0.f);
            v.z = fmaxf(v.z + b1[gn+2], 0.f);
            v.w = fmaxf(v.w + b1[gn+3], 0.f);
            __half2 h01 = __floats2half2_rn(v.x, v.y);
            __half2 h23 = __floats2half2_rn(v.z, v.w);
            __half2* p = (__half2*)&g_hidden_h[(size_t)(gm_base + i*16 + rr) * C_HID + gn];
            p[0] = h01; p[1] = h23;
        }
        __syncwarp();
    }
}

// ------------------------------------------------------------
// GEMM2: out = relu([hidden | xt | interp] @ Wcat + bcat)  K=640, N=128
// ------------------------------------------------------------
__global__ __launch_bounds__(256, 2)
void gemm2_kernel(float* __restrict__ out)
{
    extern __shared__ __align__(16) __half sh[];
    const int m0 = blockIdx.x * 128;
    const int tid = threadIdx.x;
    const int w   = tid >> 5;
    const int warp_m = w & 3;
    const int warp_n = w >> 2;
    const int lane = tid & 31;

    FragC fc[2][4];
    #pragma unroll
    for (int i = 0; i < 2; ++i)
        #pragma unroll
        for (int j = 0; j < 4; ++j)
            wmma::fill_fragment(fc[i][j], 0.f);

    auto stage_it = [&](int it) {
        const int kc = it * KC;
        const __half* ab; int as, ao;
        if      (kc < 256) { ab = g_hidden_h; as = C_HID; ao = kc;       }
        else if (kc < 384) { ab = g_xt_h;     as = C_TGT; ao = kc - 256; }
        else               { ab = g_interp_h; as = C_SRC; ao = kc - 384; }
        __half* st = sh + (it % PIPE) * STG_H;
        stage_tiles(st, st + SA_HSZ, tid, m0, ab, as, ao, g_Wcat_h, C_OUT, kc, 0);
        cp_commit();
    };

    const int NITER = (C_HID + C_IN) / KC;   // 20
    stage_it(0);
    stage_it(1);

    for (int it = 0; it < NITER; ++it) {
        cp_wait<1>();
        __syncthreads();
        if (it + 2 < NITER) stage_it(it + 2);
        const __half* st = sh + (it % PIPE) * STG_H;
        compute_chunk(st, st + SA_HSZ, warp_m, warp_n, fc);
    }
    __syncthreads();

    // epilogue: bcat + relu -> fp32 out
    float* wb = (float*)sh + w * 1024;
    const int gm_base = m0 + warp_m * 32;
    const int gn_base = warp_n * 64;
    #pragma unroll
    for (int i = 0; i < 2; ++i) {
        #pragma unroll
        for (int j = 0; j < 4; ++j)
            wmma::store_matrix_sync(wb + j*16, fc[i][j], 64, wmma::mem_row_major);
        __syncwarp();
        #pragma unroll
        for (int e = lane; e < 256; e += 32) {
            const int rr = e >> 4;
            const int cc = (e & 15) << 2;
            float4 v = *(float4*)(wb + rr*64 + cc);
            const int gn = gn_base + cc;
            v.x = fmaxf(v.x + g_bcat[gn+0], 0.f);
            v.y = fmaxf(v.y + g_bcat[gn+1], 0.f);
            v.z = fmaxf(v.z + g_bcat[gn+2], 0.f);
            v.w = fmaxf(v.w + g_bcat[gn+3], 0.f);
            *(float4*)(&out[(size_t)(gm_base + i*16 + rr) * C_OUT + gn]) = v;
        }
        __syncwarp();
    }
}

// ============================================================
// Launch.
// ============================================================
extern "C" void kernel_launch(void* const* d_in, const int* in_sizes, int n_in,
                              void* d_out, int out_size)
{
    const float* xt = (const float*)d_in[0];
    const float* pt = (const float*)d_in[1];
    const float* xs = (const float*)d_in[3];
    const float* ps = (const float*)d_in[4];
    const float* W1 = (const float*)d_in[6];
    const float* b1 = (const float*)d_in[7];
    const float* W2 = (const float*)d_in[8];
    const float* b2 = (const float*)d_in[9];
    const float* Ws = (const float*)d_in[10];
    const float* bs = (const float*)d_in[11];
    float* out = (float*)d_out;

    cudaFuncSetAttribute(gemm1_kernel, cudaFuncAttributeMaxDynamicSharedMemorySize, SMEM_BYTES);
    cudaFuncSetAttribute(gemm2_kernel, cudaFuncAttributeMaxDynamicSharedMemorySize, SMEM_BYTES);

    cvt_xt_kernel     <<<NTOT * C_TGT / 4 / 256, 256>>>(xt);
    cvt_weights_kernel<<<(C_IN * C_HID + 255) / 256, 256>>>(W1, W2, Ws, b2, bs);
    knn_kernel        <<<BATCH * (NT / 256), 256>>>(pt, ps);
    interp_kernel     <<<NTOT / 8, 256>>>(xs);
    gemm1_kernel      <<<dim3(NTOT / 128, C_HID / 128), 256, SMEM_BYTES>>>(b1);
    gemm2_kernel      <<<dim3(NTOT / 128, 1), 256, SMEM_BYTES>>>(out);
}